// round 11
// baseline (speedup 1.0000x reference)
#include <cuda_runtime.h>
#include <math.h>
#include <stdint.h>

#define Nn 50000
#define Ee 1600000
#define EP 1650000          // Ee + Nn self loops
#define ELLW 128            // padded row width (deg ~ Poisson(33); max ~60 on this input)
#define CACHE_MAX 128
#define WPB 4               // warps per block in edge kernels

// ---------------- device scratch (static, no allocation) ----------------
__device__ int   g_deg[Nn];
__device__ int   g_esrc[(size_t)Nn * ELLW];  // src per dst row (SoA)
__device__ int   g_eeid[(size_t)Nn * ELLW];  // edge id per dst row (SoA)
__device__ float g_h [Nn * 128];
__device__ float g_x1[Nn * 128];
__device__ float g_h2[Nn * 32];
__device__ float g_asrc[Nn * 4];
__device__ float g_adst[Nn * 4];
__device__ float g_as2[Nn];
__device__ float g_ad2[Nn];

// ---------------- helpers ----------------
__device__ __forceinline__ float lrelu(float x) { return x > 0.f ? x : 0.2f * x; }

// FMA-only exp (no MUFU). Valid for x <= ~30; clamps below -80 (result ~0).
__device__ __forceinline__ float fexp(float x) {
    x = fmaxf(x, -80.0f);
    float t = x * 1.4426950408889634f;
    float r = t + 12582912.0f;                 // round-to-nearest via magic number
    int   n = __float_as_int(r) - 0x4B400000;
    float f = t - (r - 12582912.0f);           // f in [-0.5, 0.5]
    float p = 0.0013333558f;
    p = fmaf(p, f, 0.0096181291f);
    p = fmaf(p, f, 0.0555041087f);
    p = fmaf(p, f, 0.2402265070f);
    p = fmaf(p, f, 0.6931471806f);
    p = fmaf(p, f, 1.0f);
    return __int_as_float((n + 127) << 23) * p;
}

__device__ __forceinline__ void ffma2(unsigned long long& d, unsigned long long a,
                                      unsigned long long b) {
    asm("fma.rn.f32x2 %0, %1, %2, %0;" : "+l"(d) : "l"(a), "l"(b));
}
__device__ __forceinline__ unsigned long long pack2(float v) {
    unsigned long long p;
    asm("mov.b64 %0, {%1, %1};" : "=l"(p) : "r"(__float_as_uint(v)));
    return p;
}

// ---------------- ELL build (2 kernels) ----------------
__global__ void k_zero() {
    int i = blockIdx.x * blockDim.x + threadIdx.x;
    if (i < Nn) g_deg[i] = 0;
}

__global__ void k_fill(const int* __restrict__ ei) {
    int e = blockIdx.x * blockDim.x + threadIdx.x;
    if (e >= EP) return;
    int src, dst;
    if (e < Ee) { src = ei[e]; dst = ei[Ee + e]; }
    else        { src = dst = e - Ee; }
    int slot = atomicAdd(&g_deg[dst], 1);
    if (slot < ELLW) {
        size_t p = (size_t)dst * ELLW + slot;
        g_esrc[p] = src;
        g_eeid[p] = e;
    }
}

// ---------------- GEMM 128x128, W staged in SMEM, fused alpha epilogue ----------
__global__ void k_gemm128(const float* __restrict__ X, const float* __restrict__ W,
                          float* __restrict__ Y,
                          const float* __restrict__ as, const float* __restrict__ ad) {
    extern __shared__ float dyn[];
    float* ws = dyn;                               // [128][128]
    float (*xs)[129] = reinterpret_cast<float (*)[129]>(dyn + 128 * 128);
    int ct = threadIdx.x & 15, rt = threadIdx.x >> 4;
    int lane = threadIdx.x & 31;
    int row0 = blockIdx.x * 64;
    for (int idx = threadIdx.x; idx < 128 * 32; idx += 256)
        reinterpret_cast<float4*>(ws)[idx] = reinterpret_cast<const float4*>(W)[idx];
    for (int idx = threadIdx.x; idx < 64 * 128; idx += 256) {
        int r = idx >> 7, c = idx & 127;
        int gr = row0 + r;
        xs[r][c] = (gr < Nn) ? X[gr * 128 + c] : 0.f;
    }
    __syncthreads();
    int r0 = rt * 4, c0 = ct * 8;
    unsigned long long acc[4][4];
    #pragma unroll
    for (int r = 0; r < 4; r++)
        #pragma unroll
        for (int c = 0; c < 4; c++) acc[r][c] = 0ull;

    const float* wsc = ws + c0;
    #pragma unroll 2
    for (int k = 0; k < 128; k++) {
        ulonglong2 wa = *reinterpret_cast<const ulonglong2*>(wsc + k * 128);
        ulonglong2 wb = *reinterpret_cast<const ulonglong2*>(wsc + k * 128 + 4);
        #pragma unroll
        for (int r = 0; r < 4; r++) {
            unsigned long long xp = pack2(xs[r0 + r][k]);
            ffma2(acc[r][0], xp, wa.x);
            ffma2(acc[r][1], xp, wa.y);
            ffma2(acc[r][2], xp, wb.x);
            ffma2(acc[r][3], xp, wb.y);
        }
    }
    float asv[8], adv[8];
    #pragma unroll
    for (int c = 0; c < 8; c++) { asv[c] = as[c0 + c]; adv[c] = ad[c0 + c]; }
    int head = ct >> 2;

    #pragma unroll
    for (int r = 0; r < 4; r++) {
        int gr = row0 + r0 + r;
        float o[8];
        #pragma unroll
        for (int c = 0; c < 4; c++)
            asm("mov.b64 {%0, %1}, %2;" : "=f"(o[2 * c]), "=f"(o[2 * c + 1]) : "l"(acc[r][c]));
        if (gr < Nn) {
            *reinterpret_cast<float4*>(Y + (size_t)gr * 128 + c0) =
                make_float4(o[0], o[1], o[2], o[3]);
            *reinterpret_cast<float4*>(Y + (size_t)gr * 128 + c0 + 4) =
                make_float4(o[4], o[5], o[6], o[7]);
        }
        float psA = 0.f, psD = 0.f;
        #pragma unroll
        for (int c = 0; c < 8; c++) {
            psA = fmaf(o[c], asv[c], psA);
            psD = fmaf(o[c], adv[c], psD);
        }
        psA += __shfl_xor_sync(0xffffffffu, psA, 1);
        psA += __shfl_xor_sync(0xffffffffu, psA, 2);
        psD += __shfl_xor_sync(0xffffffffu, psD, 1);
        psD += __shfl_xor_sync(0xffffffffu, psD, 2);
        if ((lane & 3) == 0 && gr < Nn) {
            g_asrc[gr * 4 + head] = psA;
            g_adst[gr * 4 + head] = psD;
        }
    }
}

// ---------------- GEMM: Y[N,32] = X[N,128] @ W[128,32], fused alpha1 ----------
__global__ void k_gemm32(const float* __restrict__ X, const float* __restrict__ W,
                         float* __restrict__ Y,
                         const float* __restrict__ as, const float* __restrict__ ad) {
    constexpr int CG = 8;
    constexpr int RT = 64;
    __shared__ float xs[RT][129];
    __shared__ float wsm[128 * 32];
    int tx = threadIdx.x % CG;
    int ty = threadIdx.x / CG;
    int lane = threadIdx.x & 31;
    int row0 = blockIdx.x * RT;
    for (int idx = threadIdx.x; idx < 128 * 8; idx += 512)
        reinterpret_cast<float4*>(wsm)[idx] = reinterpret_cast<const float4*>(W)[idx];
    for (int idx = threadIdx.x; idx < RT * 128; idx += 512) {
        int r = idx >> 7, c = idx & 127;
        int gr = row0 + r;
        xs[r][c] = (gr < Nn) ? X[gr * 128 + c] : 0.f;
    }
    __syncthreads();
    float4 acc = make_float4(0.f, 0.f, 0.f, 0.f);
    #pragma unroll 16
    for (int k = 0; k < 128; k++) {
        float xv = xs[ty][k];
        float4 w4 = *reinterpret_cast<const float4*>(wsm + k * 32 + tx * 4);
        acc.x = fmaf(xv, w4.x, acc.x);
        acc.y = fmaf(xv, w4.y, acc.y);
        acc.z = fmaf(xv, w4.z, acc.z);
        acc.w = fmaf(xv, w4.w, acc.w);
    }
    int gr = row0 + ty;
    if (gr < Nn)
        *reinterpret_cast<float4*>(Y + gr * 32 + tx * 4) = acc;
    float4 a4 = *reinterpret_cast<const float4*>(as + tx * 4);
    float4 d4 = *reinterpret_cast<const float4*>(ad + tx * 4);
    float psA = acc.x * a4.x + acc.y * a4.y + acc.z * a4.z + acc.w * a4.w;
    float psD = acc.x * d4.x + acc.y * d4.y + acc.z * d4.z + acc.w * d4.w;
    #pragma unroll
    for (int o = 4; o; o >>= 1) {
        psA += __shfl_xor_sync(0xffffffffu, psA, o);
        psD += __shfl_xor_sync(0xffffffffu, psD, o);
    }
    if ((lane & 7) == 0 && gr < Nn) { g_as2[gr] = psA; g_ad2[gr] = psD; }
}

// ---------------- edge kernel, 4 heads x 32 ch (one warp per dst) ----------------
template<bool WRITE_ALPHA>
__global__ __launch_bounds__(WPB * 32, 12)
void k_edge4(const float* __restrict__ H, const float* __restrict__ bias,
             float* __restrict__ Xout, float* __restrict__ alpha_out) {
    __shared__ __align__(16) float cacheT[WPB][4][CACHE_MAX];  // [head][edge] alphas
    __shared__ __align__(16) int   ssm[WPB][CACHE_MAX];        // src*32
    int wl = threadIdx.x >> 5;
    int lane = threadIdx.x & 31;
    int w = (blockIdx.x * blockDim.x + threadIdx.x) >> 5;
    if (w >= Nn) return;
    int deg = min(g_deg[w], ELLW);
    const int* srow = g_esrc + (size_t)w * ELLW;
    float4 advv = *reinterpret_cast<const float4*>(g_adst + 4 * w);
    int head = lane >> 3;
    float adh = head == 0 ? advv.x : head == 1 ? advv.y : head == 2 ? advv.z : advv.w;
    const float4* H4 = reinterpret_cast<const float4*>(H);

    // stage pre-shifted src indices (coalesced int reads)
    for (int eo = lane; eo < deg; eo += 32)
        ssm[wl][eo] = srow[eo] << 5;               // src*32: gather idx = ssm + lane
    __syncwarp();

    // exp once per (edge, head); softmax shift-invariant -> no max pass
    float psum = 0.f;
    for (int eo = lane & 7; eo < deg; eo += 8) {
        int src4 = ssm[wl][eo] >> 3;               // src*4
        float ev = fexp(lrelu(__ldg(g_asrc + src4 + head) + adh));
        cacheT[wl][head][eo] = ev;
        psum += ev;
    }
    psum += __shfl_xor_sync(0xffffffffu, psum, 1);
    psum += __shfl_xor_sync(0xffffffffu, psum, 2);
    psum += __shfl_xor_sync(0xffffffffu, psum, 4);
    float inv = 1.f / psum;
    for (int eo = lane & 7; eo < deg; eo += 8)
        cacheT[wl][head][eo] *= inv;               // cache now holds alpha
    __syncwarp();

    if (WRITE_ALPHA) {
        const int* erow = g_eeid + (size_t)w * ELLW;
        for (int eo = lane; eo < deg; eo += 32) {
            int eid = erow[eo];
            float4 av = make_float4(cacheT[wl][0][eo], cacheT[wl][1][eo],
                                    cacheT[wl][2][eo], cacheT[wl][3][eo]);
            *reinterpret_cast<float4*>(alpha_out + (size_t)eid * 4) = av;
        }
    }

    // pass B: 8-way unrolled gather; packed f32x2 accumulate
    unsigned long long a01 = 0ull, a23 = 0ull;
    const float* ct = cacheT[wl][head];
    int eo = 0;
    for (; eo + 8 <= deg; eo += 8) {
        int4 sa = *reinterpret_cast<const int4*>(&ssm[wl][eo]);
        int4 sb = *reinterpret_cast<const int4*>(&ssm[wl][eo + 4]);
        float4 aa = *reinterpret_cast<const float4*>(ct + eo);
        float4 ab = *reinterpret_cast<const float4*>(ct + eo + 4);
        ulonglong2 h0 = *reinterpret_cast<const ulonglong2*>(H4 + sa.x + lane);
        ulonglong2 h1 = *reinterpret_cast<const ulonglong2*>(H4 + sa.y + lane);
        ulonglong2 h2 = *reinterpret_cast<const ulonglong2*>(H4 + sa.z + lane);
        ulonglong2 h3 = *reinterpret_cast<const ulonglong2*>(H4 + sa.w + lane);
        ulonglong2 h4 = *reinterpret_cast<const ulonglong2*>(H4 + sb.x + lane);
        ulonglong2 h5 = *reinterpret_cast<const ulonglong2*>(H4 + sb.y + lane);
        ulonglong2 h6 = *reinterpret_cast<const ulonglong2*>(H4 + sb.z + lane);
        ulonglong2 h7 = *reinterpret_cast<const ulonglong2*>(H4 + sb.w + lane);
        unsigned long long p;
        p = pack2(aa.x); ffma2(a01, p, h0.x); ffma2(a23, p, h0.y);
        p = pack2(aa.y); ffma2(a01, p, h1.x); ffma2(a23, p, h1.y);
        p = pack2(aa.z); ffma2(a01, p, h2.x); ffma2(a23, p, h2.y);
        p = pack2(aa.w); ffma2(a01, p, h3.x); ffma2(a23, p, h3.y);
        p = pack2(ab.x); ffma2(a01, p, h4.x); ffma2(a23, p, h4.y);
        p = pack2(ab.y); ffma2(a01, p, h5.x); ffma2(a23, p, h5.y);
        p = pack2(ab.z); ffma2(a01, p, h6.x); ffma2(a23, p, h6.y);
        p = pack2(ab.w); ffma2(a01, p, h7.x); ffma2(a23, p, h7.y);
    }
    for (; eo + 4 <= deg; eo += 4) {
        int4 sa = *reinterpret_cast<const int4*>(&ssm[wl][eo]);
        float4 aa = *reinterpret_cast<const float4*>(ct + eo);
        ulonglong2 h0 = *reinterpret_cast<const ulonglong2*>(H4 + sa.x + lane);
        ulonglong2 h1 = *reinterpret_cast<const ulonglong2*>(H4 + sa.y + lane);
        ulonglong2 h2 = *reinterpret_cast<const ulonglong2*>(H4 + sa.z + lane);
        ulonglong2 h3 = *reinterpret_cast<const ulonglong2*>(H4 + sa.w + lane);
        unsigned long long p;
        p = pack2(aa.x); ffma2(a01, p, h0.x); ffma2(a23, p, h0.y);
        p = pack2(aa.y); ffma2(a01, p, h1.x); ffma2(a23, p, h1.y);
        p = pack2(aa.z); ffma2(a01, p, h2.x); ffma2(a23, p, h2.y);
        p = pack2(aa.w); ffma2(a01, p, h3.x); ffma2(a23, p, h3.y);
    }
    for (; eo < deg; eo++) {
        ulonglong2 h0 = *reinterpret_cast<const ulonglong2*>(H4 + ssm[wl][eo] + lane);
        unsigned long long p = pack2(ct[eo]);
        ffma2(a01, p, h0.x); ffma2(a23, p, h0.y);
    }

    float4 acc;
    asm("mov.b64 {%0, %1}, %2;" : "=f"(acc.x), "=f"(acc.y) : "l"(a01));
    asm("mov.b64 {%0, %1}, %2;" : "=f"(acc.z), "=f"(acc.w) : "l"(a23));
    float4 b = *reinterpret_cast<const float4*>(bias + lane * 4);
    acc.x += b.x; acc.y += b.y; acc.z += b.z; acc.w += b.w;
    acc.x = acc.x > 0.f ? acc.x : expm1f(acc.x);
    acc.y = acc.y > 0.f ? acc.y : expm1f(acc.y);
    acc.z = acc.z > 0.f ? acc.z : expm1f(acc.z);
    acc.w = acc.w > 0.f ? acc.w : expm1f(acc.w);
    *reinterpret_cast<float4*>(Xout + w * 128 + lane * 4) = acc;
}

// ---------------- edge kernel, 1 head x 32 ch (final layer) ----------------
__global__ __launch_bounds__(WPB * 32, 12)
void k_edge1(const float* __restrict__ H2, const float* __restrict__ bias,
             float* __restrict__ Out) {
    __shared__ __align__(16) float cache[WPB][CACHE_MAX];
    __shared__ __align__(16) int   ssm[WPB][CACHE_MAX];
    int wl = threadIdx.x >> 5;
    int lane = threadIdx.x & 31;
    int w = (blockIdx.x * blockDim.x + threadIdx.x) >> 5;
    if (w >= Nn) return;
    int deg = min(g_deg[w], ELLW);
    const int* srow = g_esrc + (size_t)w * ELLW;
    float adv = g_ad2[w];
    float acc = 0.f;

    float psum = 0.f;
    for (int eo = lane; eo < deg; eo += 32) {
        int src = srow[eo];
        ssm[wl][eo] = src << 5;                    // src*32
        float ev = fexp(lrelu(__ldg(g_as2 + src) + adv));
        cache[wl][eo] = ev;
        psum += ev;
    }
    #pragma unroll
    for (int o = 16; o; o >>= 1) psum += __shfl_xor_sync(0xffffffffu, psum, o);
    float inv = 1.f / psum;
    for (int eo = lane; eo < deg; eo += 32) cache[wl][eo] *= inv;
    __syncwarp();
    int eo = 0;
    for (; eo + 4 <= deg; eo += 4) {
        int4 s4 = *reinterpret_cast<const int4*>(&ssm[wl][eo]);
        float4 a4 = *reinterpret_cast<const float4*>(&cache[wl][eo]);
        float h0 = H2[s4.x + lane];
        float h1 = H2[s4.y + lane];
        float h2 = H2[s4.z + lane];
        float h3 = H2[s4.w + lane];
        acc = fmaf(a4.x, h0, acc);
        acc = fmaf(a4.y, h1, acc);
        acc = fmaf(a4.z, h2, acc);
        acc = fmaf(a4.w, h3, acc);
    }
    for (; eo < deg; eo++)
        acc = fmaf(cache[wl][eo], H2[ssm[wl][eo] + lane], acc);
    Out[w * 32 + lane] = acc + bias[lane];
}

// ---------------- launch ----------------
struct AuxStreams {
    cudaStream_t s2;
    cudaEvent_t  eFork, eJoin;
    AuxStreams() {
        cudaStreamCreateWithFlags(&s2, cudaStreamNonBlocking);
        cudaEventCreateWithFlags(&eFork, cudaEventDisableTiming);
        cudaEventCreateWithFlags(&eJoin, cudaEventDisableTiming);
    }
};

extern "C" void kernel_launch(void* const* d_in, const int* in_sizes, int n_in,
                              void* d_out, int out_size) {
    const float* x   = (const float*)d_in[0];
    const int*   ei  = (const int*)  d_in[1];
    const float* W0  = (const float*)d_in[2];
    const float* as0 = (const float*)d_in[3];
    const float* ad0 = (const float*)d_in[4];
    const float* b0  = (const float*)d_in[5];
    const float* W1  = (const float*)d_in[6];
    const float* as1 = (const float*)d_in[7];
    const float* ad1 = (const float*)d_in[8];
    const float* b1  = (const float*)d_in[9];
    const float* W2  = (const float*)d_in[10];
    const float* as2 = (const float*)d_in[11];
    const float* ad2 = (const float*)d_in[12];
    const float* b2  = (const float*)d_in[13];

    float* out        = (float*)d_out;
    float* alpha0_out = out;                        // [EP, 4]
    float* final_out  = out + (size_t)EP * 4;       // [Nn, 32]

    float *p_h, *p_x1, *p_h2;
    cudaGetSymbolAddress((void**)&p_h,  g_h);
    cudaGetSymbolAddress((void**)&p_x1, g_x1);
    cudaGetSymbolAddress((void**)&p_h2, g_h2);

    const int GEMM128_SMEM = 128 * 128 * 4 + 64 * 129 * 4;   // 98560 B
    cudaFuncSetAttribute(k_gemm128, cudaFuncAttributeMaxDynamicSharedMemorySize,
                         GEMM128_SMEM);

    const int EB = WPB * 32;                 // 128 threads per edge block
    const int EGRID = (Nn + WPB - 1) / WPB;  // one warp per node

    // created once on the first (uncaptured) correctness call; reused thereafter
    static AuxStreams aux;

    // fork: ELL build on aux.s2, concurrent with layer-0 GEMM on stream 0
    cudaEventRecord(aux.eFork, 0);
    cudaStreamWaitEvent(aux.s2, aux.eFork, 0);
    k_zero<<<(Nn + 255) / 256, 256, 0, aux.s2>>>();
    k_fill<<<(EP + 255) / 256, 256, 0, aux.s2>>>(ei);
    cudaEventRecord(aux.eJoin, aux.s2);

    // layer 0 GEMM (independent of ELL build)
    k_gemm128<<<(Nn + 63) / 64, 256, GEMM128_SMEM>>>(x, W0, p_h, as0, ad0);

    // join: edge kernels need both ELL and GEMM results
    cudaStreamWaitEvent(0, aux.eJoin, 0);

    k_edge4<true><<<EGRID, EB>>>(p_h, b0, p_x1, alpha0_out);

    // layer 1
    k_gemm128<<<(Nn + 63) / 64, 256, GEMM128_SMEM>>>(p_x1, W1, p_h, as1, ad1);
    k_edge4<false><<<EGRID, EB>>>(p_h, b1, p_x1, nullptr);

    // layer 2
    k_gemm32<<<(Nn + 63) / 64, 512>>>(p_x1, W2, p_h2, as2, ad2);
    k_edge1<<<EGRID, EB>>>(p_h2, b2, final_out);
}

// round 12
// speedup vs baseline: 1.0136x; 1.0136x over previous
#include <cuda_runtime.h>
#include <math.h>
#include <stdint.h>

#define Nn 50000
#define Ee 1600000
#define EP 1650000          // Ee + Nn self loops
#define ELLW 128            // padded row width (deg ~ Poisson(33); max ~60 on this input)
#define CACHE_MAX 128
#define WPB 4               // warps per block in edge kernels

// ---------------- device scratch (static, no allocation) ----------------
__device__ int   g_deg[Nn];                  // zero-init; reset by k_edge1 tail each run
__device__ int   g_esrc[(size_t)Nn * ELLW];  // src per dst row (SoA)
__device__ int   g_eeid[(size_t)Nn * ELLW];  // edge id per dst row (SoA)
__device__ float g_h [Nn * 128];
__device__ float g_x1[Nn * 128];
__device__ float g_h2[Nn * 32];
__device__ float g_asrc[Nn * 4];
__device__ float g_adst[Nn * 4];
__device__ float g_as2[Nn];
__device__ float g_ad2[Nn];

// ---------------- helpers ----------------
__device__ __forceinline__ float lrelu(float x) { return x > 0.f ? x : 0.2f * x; }

// FMA-only exp (no MUFU). Valid for x <= ~30; clamps below -80 (result ~0).
__device__ __forceinline__ float fexp(float x) {
    x = fmaxf(x, -80.0f);
    float t = x * 1.4426950408889634f;
    float r = t + 12582912.0f;                 // round-to-nearest via magic number
    int   n = __float_as_int(r) - 0x4B400000;
    float f = t - (r - 12582912.0f);           // f in [-0.5, 0.5]
    float p = 0.0013333558f;
    p = fmaf(p, f, 0.0096181291f);
    p = fmaf(p, f, 0.0555041087f);
    p = fmaf(p, f, 0.2402265070f);
    p = fmaf(p, f, 0.6931471806f);
    p = fmaf(p, f, 1.0f);
    return __int_as_float((n + 127) << 23) * p;
}

__device__ __forceinline__ void ffma2(unsigned long long& d, unsigned long long a,
                                      unsigned long long b) {
    asm("fma.rn.f32x2 %0, %1, %2, %0;" : "+l"(d) : "l"(a), "l"(b));
}
__device__ __forceinline__ unsigned long long pack2(float v) {
    unsigned long long p;
    asm("mov.b64 %0, {%1, %1};" : "=l"(p) : "r"(__float_as_uint(v)));
    return p;
}

// ---------------- ELL build (single kernel; g_deg pre-zeroed) ----------------
__global__ void k_fill(const int* __restrict__ ei) {
    int e = blockIdx.x * blockDim.x + threadIdx.x;
    if (e >= EP) return;
    int src, dst;
    if (e < Ee) { src = ei[e]; dst = ei[Ee + e]; }
    else        { src = dst = e - Ee; }
    int slot = atomicAdd(&g_deg[dst], 1);
    if (slot < ELLW) {
        size_t p = (size_t)dst * ELLW + slot;
        g_esrc[p] = src;
        g_eeid[p] = e;
    }
}

// ---------------- GEMM 128x128, W staged in SMEM, fused alpha epilogue ----------
// X tile row-padded to 132 floats (16B-aligned rows) so the k-loop reads
// X as float4 per 4-k group: 9 LDS wavefronts/warp/k instead of 12.
__global__ void k_gemm128(const float* __restrict__ X, const float* __restrict__ W,
                          float* __restrict__ Y,
                          const float* __restrict__ as, const float* __restrict__ ad) {
    extern __shared__ float dyn[];
    float* ws = dyn;                               // [128][128]
    float* xs = dyn + 128 * 128;                   // [64][132]
    int ct = threadIdx.x & 15, rt = threadIdx.x >> 4;
    int lane = threadIdx.x & 31;
    int row0 = blockIdx.x * 64;
    for (int idx = threadIdx.x; idx < 128 * 32; idx += 256)
        reinterpret_cast<float4*>(ws)[idx] = reinterpret_cast<const float4*>(W)[idx];
    for (int idx = threadIdx.x; idx < 64 * 128; idx += 256) {
        int r = idx >> 7, c = idx & 127;
        int gr = row0 + r;
        xs[r * 132 + c] = (gr < Nn) ? X[(size_t)gr * 128 + c] : 0.f;
    }
    __syncthreads();
    int r0 = rt * 4, c0 = ct * 8;
    unsigned long long acc[4][4];
    #pragma unroll
    for (int r = 0; r < 4; r++)
        #pragma unroll
        for (int c = 0; c < 4; c++) acc[r][c] = 0ull;

    const float* wsc = ws + c0;
    for (int k4 = 0; k4 < 32; k4++) {
        int k = k4 * 4;
        float4 xv[4];
        #pragma unroll
        for (int r = 0; r < 4; r++)
            xv[r] = *reinterpret_cast<const float4*>(xs + (r0 + r) * 132 + k);
        #pragma unroll
        for (int kk = 0; kk < 4; kk++) {
            ulonglong2 wa = *reinterpret_cast<const ulonglong2*>(wsc + (k + kk) * 128);
            ulonglong2 wb = *reinterpret_cast<const ulonglong2*>(wsc + (k + kk) * 128 + 4);
            #pragma unroll
            for (int r = 0; r < 4; r++) {
                float xsc = kk == 0 ? xv[r].x : kk == 1 ? xv[r].y
                          : kk == 2 ? xv[r].z : xv[r].w;
                unsigned long long xp = pack2(xsc);
                ffma2(acc[r][0], xp, wa.x);
                ffma2(acc[r][1], xp, wa.y);
                ffma2(acc[r][2], xp, wb.x);
                ffma2(acc[r][3], xp, wb.y);
            }
        }
    }
    float asv[8], adv[8];
    #pragma unroll
    for (int c = 0; c < 8; c++) { asv[c] = as[c0 + c]; adv[c] = ad[c0 + c]; }
    int head = ct >> 2;

    #pragma unroll
    for (int r = 0; r < 4; r++) {
        int gr = row0 + r0 + r;
        float o[8];
        #pragma unroll
        for (int c = 0; c < 4; c++)
            asm("mov.b64 {%0, %1}, %2;" : "=f"(o[2 * c]), "=f"(o[2 * c + 1]) : "l"(acc[r][c]));
        if (gr < Nn) {
            *reinterpret_cast<float4*>(Y + (size_t)gr * 128 + c0) =
                make_float4(o[0], o[1], o[2], o[3]);
            *reinterpret_cast<float4*>(Y + (size_t)gr * 128 + c0 + 4) =
                make_float4(o[4], o[5], o[6], o[7]);
        }
        float psA = 0.f, psD = 0.f;
        #pragma unroll
        for (int c = 0; c < 8; c++) {
            psA = fmaf(o[c], asv[c], psA);
            psD = fmaf(o[c], adv[c], psD);
        }
        psA += __shfl_xor_sync(0xffffffffu, psA, 1);
        psA += __shfl_xor_sync(0xffffffffu, psA, 2);
        psD += __shfl_xor_sync(0xffffffffu, psD, 1);
        psD += __shfl_xor_sync(0xffffffffu, psD, 2);
        if ((lane & 3) == 0 && gr < Nn) {
            g_asrc[gr * 4 + head] = psA;
            g_adst[gr * 4 + head] = psD;
        }
    }
}

// ---------------- GEMM: Y[N,32] = X[N,128] @ W[128,32], fused alpha1 ----------
__global__ void k_gemm32(const float* __restrict__ X, const float* __restrict__ W,
                         float* __restrict__ Y,
                         const float* __restrict__ as, const float* __restrict__ ad) {
    constexpr int CG = 8;
    constexpr int RT = 64;
    __shared__ float xs[RT][129];
    __shared__ float wsm[128 * 32];
    int tx = threadIdx.x % CG;
    int ty = threadIdx.x / CG;
    int lane = threadIdx.x & 31;
    int row0 = blockIdx.x * RT;
    for (int idx = threadIdx.x; idx < 128 * 8; idx += 512)
        reinterpret_cast<float4*>(wsm)[idx] = reinterpret_cast<const float4*>(W)[idx];
    for (int idx = threadIdx.x; idx < RT * 128; idx += 512) {
        int r = idx >> 7, c = idx & 127;
        int gr = row0 + r;
        xs[r][c] = (gr < Nn) ? X[gr * 128 + c] : 0.f;
    }
    __syncthreads();
    float4 acc = make_float4(0.f, 0.f, 0.f, 0.f);
    #pragma unroll 16
    for (int k = 0; k < 128; k++) {
        float xv = xs[ty][k];
        float4 w4 = *reinterpret_cast<const float4*>(wsm + k * 32 + tx * 4);
        acc.x = fmaf(xv, w4.x, acc.x);
        acc.y = fmaf(xv, w4.y, acc.y);
        acc.z = fmaf(xv, w4.z, acc.z);
        acc.w = fmaf(xv, w4.w, acc.w);
    }
    int gr = row0 + ty;
    if (gr < Nn)
        *reinterpret_cast<float4*>(Y + gr * 32 + tx * 4) = acc;
    float4 a4 = *reinterpret_cast<const float4*>(as + tx * 4);
    float4 d4 = *reinterpret_cast<const float4*>(ad + tx * 4);
    float psA = acc.x * a4.x + acc.y * a4.y + acc.z * a4.z + acc.w * a4.w;
    float psD = acc.x * d4.x + acc.y * d4.y + acc.z * d4.z + acc.w * d4.w;
    #pragma unroll
    for (int o = 4; o; o >>= 1) {
        psA += __shfl_xor_sync(0xffffffffu, psA, o);
        psD += __shfl_xor_sync(0xffffffffu, psD, o);
    }
    if ((lane & 7) == 0 && gr < Nn) { g_as2[gr] = psA; g_ad2[gr] = psD; }
}

// ---------------- edge kernel, 4 heads x 32 ch (one warp per dst) ----------------
template<bool WRITE_ALPHA>
__global__ __launch_bounds__(WPB * 32, 12)
void k_edge4(const float* __restrict__ H, const float* __restrict__ bias,
             float* __restrict__ Xout, float* __restrict__ alpha_out) {
    __shared__ __align__(16) float cacheT[WPB][4][CACHE_MAX];  // [head][edge] alphas
    __shared__ __align__(16) int   ssm[WPB][CACHE_MAX];        // src*32
    int wl = threadIdx.x >> 5;
    int lane = threadIdx.x & 31;
    int w = (blockIdx.x * blockDim.x + threadIdx.x) >> 5;
    if (w >= Nn) return;
    int deg = min(g_deg[w], ELLW);
    const int* srow = g_esrc + (size_t)w * ELLW;
    float4 advv = *reinterpret_cast<const float4*>(g_adst + 4 * w);
    int head = lane >> 3;
    float adh = head == 0 ? advv.x : head == 1 ? advv.y : head == 2 ? advv.z : advv.w;
    const float4* H4 = reinterpret_cast<const float4*>(H);

    for (int eo = lane; eo < deg; eo += 32)
        ssm[wl][eo] = srow[eo] << 5;               // src*32: gather idx = ssm + lane
    __syncwarp();

    float psum = 0.f;
    for (int eo = lane & 7; eo < deg; eo += 8) {
        int src4 = ssm[wl][eo] >> 3;               // src*4
        float ev = fexp(lrelu(__ldg(g_asrc + src4 + head) + adh));
        cacheT[wl][head][eo] = ev;
        psum += ev;
    }
    psum += __shfl_xor_sync(0xffffffffu, psum, 1);
    psum += __shfl_xor_sync(0xffffffffu, psum, 2);
    psum += __shfl_xor_sync(0xffffffffu, psum, 4);
    float inv = 1.f / psum;
    for (int eo = lane & 7; eo < deg; eo += 8)
        cacheT[wl][head][eo] *= inv;               // cache now holds alpha
    __syncwarp();

    if (WRITE_ALPHA) {
        const int* erow = g_eeid + (size_t)w * ELLW;
        for (int eo = lane; eo < deg; eo += 32) {
            int eid = erow[eo];
            float4 av = make_float4(cacheT[wl][0][eo], cacheT[wl][1][eo],
                                    cacheT[wl][2][eo], cacheT[wl][3][eo]);
            *reinterpret_cast<float4*>(alpha_out + (size_t)eid * 4) = av;
        }
    }

    unsigned long long a01 = 0ull, a23 = 0ull;
    const float* ct = cacheT[wl][head];
    int eo = 0;
    for (; eo + 8 <= deg; eo += 8) {
        int4 sa = *reinterpret_cast<const int4*>(&ssm[wl][eo]);
        int4 sb = *reinterpret_cast<const int4*>(&ssm[wl][eo + 4]);
        float4 aa = *reinterpret_cast<const float4*>(ct + eo);
        float4 ab = *reinterpret_cast<const float4*>(ct + eo + 4);
        ulonglong2 h0 = *reinterpret_cast<const ulonglong2*>(H4 + sa.x + lane);
        ulonglong2 h1 = *reinterpret_cast<const ulonglong2*>(H4 + sa.y + lane);
        ulonglong2 h2 = *reinterpret_cast<const ulonglong2*>(H4 + sa.z + lane);
        ulonglong2 h3 = *reinterpret_cast<const ulonglong2*>(H4 + sa.w + lane);
        ulonglong2 h4 = *reinterpret_cast<const ulonglong2*>(H4 + sb.x + lane);
        ulonglong2 h5 = *reinterpret_cast<const ulonglong2*>(H4 + sb.y + lane);
        ulonglong2 h6 = *reinterpret_cast<const ulonglong2*>(H4 + sb.z + lane);
        ulonglong2 h7 = *reinterpret_cast<const ulonglong2*>(H4 + sb.w + lane);
        unsigned long long p;
        p = pack2(aa.x); ffma2(a01, p, h0.x); ffma2(a23, p, h0.y);
        p = pack2(aa.y); ffma2(a01, p, h1.x); ffma2(a23, p, h1.y);
        p = pack2(aa.z); ffma2(a01, p, h2.x); ffma2(a23, p, h2.y);
        p = pack2(aa.w); ffma2(a01, p, h3.x); ffma2(a23, p, h3.y);
        p = pack2(ab.x); ffma2(a01, p, h4.x); ffma2(a23, p, h4.y);
        p = pack2(ab.y); ffma2(a01, p, h5.x); ffma2(a23, p, h5.y);
        p = pack2(ab.z); ffma2(a01, p, h6.x); ffma2(a23, p, h6.y);
        p = pack2(ab.w); ffma2(a01, p, h7.x); ffma2(a23, p, h7.y);
    }
    for (; eo + 4 <= deg; eo += 4) {
        int4 sa = *reinterpret_cast<const int4*>(&ssm[wl][eo]);
        float4 aa = *reinterpret_cast<const float4*>(ct + eo);
        ulonglong2 h0 = *reinterpret_cast<const ulonglong2*>(H4 + sa.x + lane);
        ulonglong2 h1 = *reinterpret_cast<const ulonglong2*>(H4 + sa.y + lane);
        ulonglong2 h2 = *reinterpret_cast<const ulonglong2*>(H4 + sa.z + lane);
        ulonglong2 h3 = *reinterpret_cast<const ulonglong2*>(H4 + sa.w + lane);
        unsigned long long p;
        p = pack2(aa.x); ffma2(a01, p, h0.x); ffma2(a23, p, h0.y);
        p = pack2(aa.y); ffma2(a01, p, h1.x); ffma2(a23, p, h1.y);
        p = pack2(aa.z); ffma2(a01, p, h2.x); ffma2(a23, p, h2.y);
        p = pack2(aa.w); ffma2(a01, p, h3.x); ffma2(a23, p, h3.y);
    }
    for (; eo < deg; eo++) {
        ulonglong2 h0 = *reinterpret_cast<const ulonglong2*>(H4 + ssm[wl][eo] + lane);
        unsigned long long p = pack2(ct[eo]);
        ffma2(a01, p, h0.x); ffma2(a23, p, h0.y);
    }

    float4 acc;
    asm("mov.b64 {%0, %1}, %2;" : "=f"(acc.x), "=f"(acc.y) : "l"(a01));
    asm("mov.b64 {%0, %1}, %2;" : "=f"(acc.z), "=f"(acc.w) : "l"(a23));
    float4 b = *reinterpret_cast<const float4*>(bias + lane * 4);
    acc.x += b.x; acc.y += b.y; acc.z += b.z; acc.w += b.w;
    acc.x = acc.x > 0.f ? acc.x : expm1f(acc.x);
    acc.y = acc.y > 0.f ? acc.y : expm1f(acc.y);
    acc.z = acc.z > 0.f ? acc.z : expm1f(acc.z);
    acc.w = acc.w > 0.f ? acc.w : expm1f(acc.w);
    *reinterpret_cast<float4*>(Xout + w * 128 + lane * 4) = acc;
}

// ---------------- edge kernel, 1 head x 32 ch (final layer) ----------------
// Tail: resets g_deg[w] = 0 so the next replay starts from a clean state
// (g_deg is statically zero-initialized for the very first run).
__global__ __launch_bounds__(WPB * 32, 12)
void k_edge1(const float* __restrict__ H2, const float* __restrict__ bias,
             float* __restrict__ Out) {
    __shared__ __align__(16) float cache[WPB][CACHE_MAX];
    __shared__ __align__(16) int   ssm[WPB][CACHE_MAX];
    int wl = threadIdx.x >> 5;
    int lane = threadIdx.x & 31;
    int w = (blockIdx.x * blockDim.x + threadIdx.x) >> 5;
    if (w >= Nn) return;
    int deg = min(g_deg[w], ELLW);
    const int* srow = g_esrc + (size_t)w * ELLW;
    float adv = g_ad2[w];
    float acc = 0.f;

    float psum = 0.f;
    for (int eo = lane; eo < deg; eo += 32) {
        int src = srow[eo];
        ssm[wl][eo] = src << 5;                    // src*32
        float ev = fexp(lrelu(__ldg(g_as2 + src) + adv));
        cache[wl][eo] = ev;
        psum += ev;
    }
    #pragma unroll
    for (int o = 16; o; o >>= 1) psum += __shfl_xor_sync(0xffffffffu, psum, o);
    float inv = 1.f / psum;
    for (int eo = lane; eo < deg; eo += 32) cache[wl][eo] *= inv;
    __syncwarp();
    int eo = 0;
    for (; eo + 4 <= deg; eo += 4) {
        int4 s4 = *reinterpret_cast<const int4*>(&ssm[wl][eo]);
        float4 a4 = *reinterpret_cast<const float4*>(&cache[wl][eo]);
        float h0 = H2[s4.x + lane];
        float h1 = H2[s4.y + lane];
        float h2 = H2[s4.z + lane];
        float h3 = H2[s4.w + lane];
        acc = fmaf(a4.x, h0, acc);
        acc = fmaf(a4.y, h1, acc);
        acc = fmaf(a4.z, h2, acc);
        acc = fmaf(a4.w, h3, acc);
    }
    for (; eo < deg; eo++)
        acc = fmaf(cache[wl][eo], H2[ssm[wl][eo] + lane], acc);
    Out[w * 32 + lane] = acc + bias[lane];
    if (lane == 0) g_deg[w] = 0;                   // reset for next replay
}

// ---------------- launch ----------------
extern "C" void kernel_launch(void* const* d_in, const int* in_sizes, int n_in,
                              void* d_out, int out_size) {
    const float* x   = (const float*)d_in[0];
    const int*   ei  = (const int*)  d_in[1];
    const float* W0  = (const float*)d_in[2];
    const float* as0 = (const float*)d_in[3];
    const float* ad0 = (const float*)d_in[4];
    const float* b0  = (const float*)d_in[5];
    const float* W1  = (const float*)d_in[6];
    const float* as1 = (const float*)d_in[7];
    const float* ad1 = (const float*)d_in[8];
    const float* b1  = (const float*)d_in[9];
    const float* W2  = (const float*)d_in[10];
    const float* as2 = (const float*)d_in[11];
    const float* ad2 = (const float*)d_in[12];
    const float* b2  = (const float*)d_in[13];

    float* out        = (float*)d_out;
    float* alpha0_out = out;                        // [EP, 4]
    float* final_out  = out + (size_t)EP * 4;       // [Nn, 32]

    float *p_h, *p_x1, *p_h2;
    cudaGetSymbolAddress((void**)&p_h,  g_h);
    cudaGetSymbolAddress((void**)&p_x1, g_x1);
    cudaGetSymbolAddress((void**)&p_h2, g_h2);

    const int GEMM128_SMEM = 128 * 128 * 4 + 64 * 132 * 4;   // 99328 B
    cudaFuncSetAttribute(k_gemm128, cudaFuncAttributeMaxDynamicSharedMemorySize,
                         GEMM128_SMEM);

    const int EB = WPB * 32;                 // 128 threads per edge block
    const int EGRID = (Nn + WPB - 1) / WPB;  // one warp per node

    // (1) ELL build — g_deg zeroed by previous run's k_edge1 (or static init)
    k_fill<<<(EP + 255) / 256, 256>>>(ei);

    // (2) layer 0 GEMM
    k_gemm128<<<(Nn + 63) / 64, 256, GEMM128_SMEM>>>(x, W0, p_h, as0, ad0);

    // (3) layer 0 edge
    k_edge4<true><<<EGRID, EB>>>(p_h, b0, p_x1, alpha0_out);

    // (4) layer 1 GEMM  <- lands in the profiler's sampled slot
    k_gemm128<<<(Nn + 63) / 64, 256, GEMM128_SMEM>>>(p_x1, W1, p_h, as1, ad1);

    // (5) layer 1 edge
    k_edge4<false><<<EGRID, EB>>>(p_h, b1, p_x1, nullptr);

    // (6,7) layer 2
    k_gemm32<<<(Nn + 63) / 64, 512>>>(p_x1, W2, p_h2, as2, ad2);
    k_edge1<<<EGRID, EB>>>(p_h2, b2, final_out);
}

// round 13
// speedup vs baseline: 1.1509x; 1.1354x over previous
#include <cuda_runtime.h>
#include <math.h>
#include <stdint.h>

#define Nn 50000
#define Ee 1600000
#define EP 1650000          // Ee + Nn self loops
#define ELLW 128            // padded row width (deg ~ Poisson(33); max ~60 on this input)
#define CACHE_MAX 128
#define WPB 4               // warps per block in edge kernels

// ---------------- device scratch (static, no allocation) ----------------
__device__ int   g_deg[Nn];                  // zero-init; reset by k_edge1 tail each run
__device__ int   g_esrc[(size_t)Nn * ELLW];  // src per dst row (SoA)
__device__ int   g_eeid[(size_t)Nn * ELLW];  // edge id per dst row (SoA)
__device__ float g_h [Nn * 128];
__device__ float g_x1[Nn * 128];
__device__ float g_h2[Nn * 32];
__device__ float g_asrc[Nn * 4];
__device__ float g_adst[Nn * 4];
__device__ float g_as2[Nn];
__device__ float g_ad2[Nn];

// ---------------- helpers ----------------
__device__ __forceinline__ float lrelu(float x) { return x > 0.f ? x : 0.2f * x; }

// FMA-only exp (no MUFU). Valid for x <= ~30; clamps below -80 (result ~0).
__device__ __forceinline__ float fexp(float x) {
    x = fmaxf(x, -80.0f);
    float t = x * 1.4426950408889634f;
    float r = t + 12582912.0f;                 // round-to-nearest via magic number
    int   n = __float_as_int(r) - 0x4B400000;
    float f = t - (r - 12582912.0f);           // f in [-0.5, 0.5]
    float p = 0.0013333558f;
    p = fmaf(p, f, 0.0096181291f);
    p = fmaf(p, f, 0.0555041087f);
    p = fmaf(p, f, 0.2402265070f);
    p = fmaf(p, f, 0.6931471806f);
    p = fmaf(p, f, 1.0f);
    return __int_as_float((n + 127) << 23) * p;
}

__device__ __forceinline__ void ffma2(unsigned long long& d, unsigned long long a,
                                      unsigned long long b) {
    asm("fma.rn.f32x2 %0, %1, %2, %0;" : "+l"(d) : "l"(a), "l"(b));
}
__device__ __forceinline__ unsigned long long pack2(float v) {
    unsigned long long p;
    asm("mov.b64 %0, {%1, %1};" : "=l"(p) : "r"(__float_as_uint(v)));
    return p;
}

// ---------------- ELL build (single kernel; g_deg pre-zeroed) ----------------
__global__ void k_fill(const int* __restrict__ ei) {
    int e = blockIdx.x * blockDim.x + threadIdx.x;
    if (e >= EP) return;
    int src, dst;
    if (e < Ee) { src = ei[e]; dst = ei[Ee + e]; }
    else        { src = dst = e - Ee; }
    int slot = atomicAdd(&g_deg[dst], 1);
    if (slot < ELLW) {
        size_t p = (size_t)dst * ELLW + slot;
        g_esrc[p] = src;
        g_eeid[p] = e;
    }
}

// ---------------- GEMM 128x128, W staged in SMEM, fused alpha epilogue ----------
// Per-thread cols split into TWO 4-col groups (ct*4 and 64+ct*4) so W LDS
// addresses are 16B-spaced -> conflict-free (was 32B-spaced -> 4-way conflict).
// X tile rows padded to 132 floats; X read as float4 per 4-k group.
__global__ void k_gemm128(const float* __restrict__ X, const float* __restrict__ W,
                          float* __restrict__ Y,
                          const float* __restrict__ as, const float* __restrict__ ad) {
    extern __shared__ float dyn[];
    float* ws = dyn;                               // [128][128]
    float* xs = dyn + 128 * 128;                   // [64][132]
    int ct = threadIdx.x & 15, rt = threadIdx.x >> 4;
    int lane = threadIdx.x & 31;
    int row0 = blockIdx.x * 64;
    for (int idx = threadIdx.x; idx < 128 * 32; idx += 256)
        reinterpret_cast<float4*>(ws)[idx] = reinterpret_cast<const float4*>(W)[idx];
    for (int idx = threadIdx.x; idx < 64 * 128; idx += 256) {
        int r = idx >> 7, c = idx & 127;
        int gr = row0 + r;
        xs[r * 132 + c] = (gr < Nn) ? X[(size_t)gr * 128 + c] : 0.f;
    }
    __syncthreads();
    int r0 = rt * 4;
    int cA = ct * 4;            // group A cols [cA, cA+3]   (heads 0-1)
    int cB = 64 + ct * 4;       // group B cols [cB, cB+3]   (heads 2-3)
    unsigned long long acc[4][4];   // [row][A0,A1,B0,B1]
    #pragma unroll
    for (int r = 0; r < 4; r++)
        #pragma unroll
        for (int c = 0; c < 4; c++) acc[r][c] = 0ull;

    const float* wsA = ws + cA;
    const float* wsB = ws + cB;
    for (int k4 = 0; k4 < 32; k4++) {
        int k = k4 * 4;
        float4 xv[4];
        #pragma unroll
        for (int r = 0; r < 4; r++)
            xv[r] = *reinterpret_cast<const float4*>(xs + (r0 + r) * 132 + k);
        #pragma unroll
        for (int kk = 0; kk < 4; kk++) {
            ulonglong2 wa = *reinterpret_cast<const ulonglong2*>(wsA + (k + kk) * 128);
            ulonglong2 wb = *reinterpret_cast<const ulonglong2*>(wsB + (k + kk) * 128);
            #pragma unroll
            for (int r = 0; r < 4; r++) {
                float xsc = kk == 0 ? xv[r].x : kk == 1 ? xv[r].y
                          : kk == 2 ? xv[r].z : xv[r].w;
                unsigned long long xp = pack2(xsc);
                ffma2(acc[r][0], xp, wa.x);
                ffma2(acc[r][1], xp, wa.y);
                ffma2(acc[r][2], xp, wb.x);
                ffma2(acc[r][3], xp, wb.y);
            }
        }
    }
    float asvA[4], advA[4], asvB[4], advB[4];
    #pragma unroll
    for (int c = 0; c < 4; c++) {
        asvA[c] = as[cA + c]; advA[c] = ad[cA + c];
        asvB[c] = as[cB + c]; advB[c] = ad[cB + c];
    }
    int headA = ct >> 3;        // 0 or 1; headB = 2 + headA

    #pragma unroll
    for (int r = 0; r < 4; r++) {
        int gr = row0 + r0 + r;
        float o[8];
        #pragma unroll
        for (int c = 0; c < 4; c++)
            asm("mov.b64 {%0, %1}, %2;" : "=f"(o[2 * c]), "=f"(o[2 * c + 1]) : "l"(acc[r][c]));
        if (gr < Nn) {
            *reinterpret_cast<float4*>(Y + (size_t)gr * 128 + cA) =
                make_float4(o[0], o[1], o[2], o[3]);
            *reinterpret_cast<float4*>(Y + (size_t)gr * 128 + cB) =
                make_float4(o[4], o[5], o[6], o[7]);
        }
        // fused alpha: head dot = 8 lanes (ct group of 8) x 4 cols
        float psAA = 0.f, psDA = 0.f, psAB = 0.f, psDB = 0.f;
        #pragma unroll
        for (int c = 0; c < 4; c++) {
            psAA = fmaf(o[c], asvA[c], psAA);
            psDA = fmaf(o[c], advA[c], psDA);
            psAB = fmaf(o[4 + c], asvB[c], psAB);
            psDB = fmaf(o[4 + c], advB[c], psDB);
        }
        #pragma unroll
        for (int off = 1; off < 8; off <<= 1) {
            psAA += __shfl_xor_sync(0xffffffffu, psAA, off);
            psDA += __shfl_xor_sync(0xffffffffu, psDA, off);
            psAB += __shfl_xor_sync(0xffffffffu, psAB, off);
            psDB += __shfl_xor_sync(0xffffffffu, psDB, off);
        }
        if ((lane & 7) == 0 && gr < Nn) {
            g_asrc[gr * 4 + headA]     = psAA;
            g_adst[gr * 4 + headA]     = psDA;
            g_asrc[gr * 4 + 2 + headA] = psAB;
            g_adst[gr * 4 + 2 + headA] = psDB;
        }
    }
}

// ---------------- GEMM: Y[N,32] = X[N,128] @ W[128,32], fused alpha1 ----------
__global__ void k_gemm32(const float* __restrict__ X, const float* __restrict__ W,
                         float* __restrict__ Y,
                         const float* __restrict__ as, const float* __restrict__ ad) {
    constexpr int CG = 8;
    constexpr int RT = 64;
    __shared__ float xs[RT][129];
    __shared__ float wsm[128 * 32];
    int tx = threadIdx.x % CG;
    int ty = threadIdx.x / CG;
    int lane = threadIdx.x & 31;
    int row0 = blockIdx.x * RT;
    for (int idx = threadIdx.x; idx < 128 * 8; idx += 512)
        reinterpret_cast<float4*>(wsm)[idx] = reinterpret_cast<const float4*>(W)[idx];
    for (int idx = threadIdx.x; idx < RT * 128; idx += 512) {
        int r = idx >> 7, c = idx & 127;
        int gr = row0 + r;
        xs[r][c] = (gr < Nn) ? X[gr * 128 + c] : 0.f;
    }
    __syncthreads();
    float4 acc = make_float4(0.f, 0.f, 0.f, 0.f);
    #pragma unroll 16
    for (int k = 0; k < 128; k++) {
        float xv = xs[ty][k];
        float4 w4 = *reinterpret_cast<const float4*>(wsm + k * 32 + tx * 4);
        acc.x = fmaf(xv, w4.x, acc.x);
        acc.y = fmaf(xv, w4.y, acc.y);
        acc.z = fmaf(xv, w4.z, acc.z);
        acc.w = fmaf(xv, w4.w, acc.w);
    }
    int gr = row0 + ty;
    if (gr < Nn)
        *reinterpret_cast<float4*>(Y + gr * 32 + tx * 4) = acc;
    float4 a4 = *reinterpret_cast<const float4*>(as + tx * 4);
    float4 d4 = *reinterpret_cast<const float4*>(ad + tx * 4);
    float psA = acc.x * a4.x + acc.y * a4.y + acc.z * a4.z + acc.w * a4.w;
    float psD = acc.x * d4.x + acc.y * d4.y + acc.z * d4.z + acc.w * d4.w;
    #pragma unroll
    for (int o = 4; o; o >>= 1) {
        psA += __shfl_xor_sync(0xffffffffu, psA, o);
        psD += __shfl_xor_sync(0xffffffffu, psD, o);
    }
    if ((lane & 7) == 0 && gr < Nn) { g_as2[gr] = psA; g_ad2[gr] = psD; }
}

// ---------------- edge kernel, 4 heads x 32 ch (one warp per dst) ----------------
template<bool WRITE_ALPHA>
__global__ __launch_bounds__(WPB * 32, 12)
void k_edge4(const float* __restrict__ H, const float* __restrict__ bias,
             float* __restrict__ Xout, float* __restrict__ alpha_out) {
    __shared__ __align__(16) float cacheT[WPB][4][CACHE_MAX];  // [head][edge] alphas
    __shared__ __align__(16) int   ssm[WPB][CACHE_MAX];        // src*32
    int wl = threadIdx.x >> 5;
    int lane = threadIdx.x & 31;
    int w = (blockIdx.x * blockDim.x + threadIdx.x) >> 5;
    if (w >= Nn) return;
    int deg = min(g_deg[w], ELLW);
    const int* srow = g_esrc + (size_t)w * ELLW;
    float4 advv = *reinterpret_cast<const float4*>(g_adst + 4 * w);
    int head = lane >> 3;
    float adh = head == 0 ? advv.x : head == 1 ? advv.y : head == 2 ? advv.z : advv.w;
    const float4* H4 = reinterpret_cast<const float4*>(H);

    for (int eo = lane; eo < deg; eo += 32)
        ssm[wl][eo] = srow[eo] << 5;               // src*32: gather idx = ssm + lane
    __syncwarp();

    float psum = 0.f;
    for (int eo = lane & 7; eo < deg; eo += 8) {
        int src4 = ssm[wl][eo] >> 3;               // src*4
        float ev = fexp(lrelu(__ldg(g_asrc + src4 + head) + adh));
        cacheT[wl][head][eo] = ev;
        psum += ev;
    }
    psum += __shfl_xor_sync(0xffffffffu, psum, 1);
    psum += __shfl_xor_sync(0xffffffffu, psum, 2);
    psum += __shfl_xor_sync(0xffffffffu, psum, 4);
    float inv = 1.f / psum;
    for (int eo = lane & 7; eo < deg; eo += 8)
        cacheT[wl][head][eo] *= inv;               // cache now holds alpha
    __syncwarp();

    if (WRITE_ALPHA) {
        const int* erow = g_eeid + (size_t)w * ELLW;
        for (int eo = lane; eo < deg; eo += 32) {
            int eid = erow[eo];
            float4 av = make_float4(cacheT[wl][0][eo], cacheT[wl][1][eo],
                                    cacheT[wl][2][eo], cacheT[wl][3][eo]);
            *reinterpret_cast<float4*>(alpha_out + (size_t)eid * 4) = av;
        }
    }

    unsigned long long a01 = 0ull, a23 = 0ull;
    const float* ct = cacheT[wl][head];
    int eo = 0;
    for (; eo + 8 <= deg; eo += 8) {
        int4 sa = *reinterpret_cast<const int4*>(&ssm[wl][eo]);
        int4 sb = *reinterpret_cast<const int4*>(&ssm[wl][eo + 4]);
        float4 aa = *reinterpret_cast<const float4*>(ct + eo);
        float4 ab = *reinterpret_cast<const float4*>(ct + eo + 4);
        ulonglong2 h0 = *reinterpret_cast<const ulonglong2*>(H4 + sa.x + lane);
        ulonglong2 h1 = *reinterpret_cast<const ulonglong2*>(H4 + sa.y + lane);
        ulonglong2 h2 = *reinterpret_cast<const ulonglong2*>(H4 + sa.z + lane);
        ulonglong2 h3 = *reinterpret_cast<const ulonglong2*>(H4 + sa.w + lane);
        ulonglong2 h4 = *reinterpret_cast<const ulonglong2*>(H4 + sb.x + lane);
        ulonglong2 h5 = *reinterpret_cast<const ulonglong2*>(H4 + sb.y + lane);
        ulonglong2 h6 = *reinterpret_cast<const ulonglong2*>(H4 + sb.z + lane);
        ulonglong2 h7 = *reinterpret_cast<const ulonglong2*>(H4 + sb.w + lane);
        unsigned long long p;
        p = pack2(aa.x); ffma2(a01, p, h0.x); ffma2(a23, p, h0.y);
        p = pack2(aa.y); ffma2(a01, p, h1.x); ffma2(a23, p, h1.y);
        p = pack2(aa.z); ffma2(a01, p, h2.x); ffma2(a23, p, h2.y);
        p = pack2(aa.w); ffma2(a01, p, h3.x); ffma2(a23, p, h3.y);
        p = pack2(ab.x); ffma2(a01, p, h4.x); ffma2(a23, p, h4.y);
        p = pack2(ab.y); ffma2(a01, p, h5.x); ffma2(a23, p, h5.y);
        p = pack2(ab.z); ffma2(a01, p, h6.x); ffma2(a23, p, h6.y);
        p = pack2(ab.w); ffma2(a01, p, h7.x); ffma2(a23, p, h7.y);
    }
    for (; eo + 4 <= deg; eo += 4) {
        int4 sa = *reinterpret_cast<const int4*>(&ssm[wl][eo]);
        float4 aa = *reinterpret_cast<const float4*>(ct + eo);
        ulonglong2 h0 = *reinterpret_cast<const ulonglong2*>(H4 + sa.x + lane);
        ulonglong2 h1 = *reinterpret_cast<const ulonglong2*>(H4 + sa.y + lane);
        ulonglong2 h2 = *reinterpret_cast<const ulonglong2*>(H4 + sa.z + lane);
        ulonglong2 h3 = *reinterpret_cast<const ulonglong2*>(H4 + sa.w + lane);
        unsigned long long p;
        p = pack2(aa.x); ffma2(a01, p, h0.x); ffma2(a23, p, h0.y);
        p = pack2(aa.y); ffma2(a01, p, h1.x); ffma2(a23, p, h1.y);
        p = pack2(aa.z); ffma2(a01, p, h2.x); ffma2(a23, p, h2.y);
        p = pack2(aa.w); ffma2(a01, p, h3.x); ffma2(a23, p, h3.y);
    }
    for (; eo < deg; eo++) {
        ulonglong2 h0 = *reinterpret_cast<const ulonglong2*>(H4 + ssm[wl][eo] + lane);
        unsigned long long p = pack2(ct[eo]);
        ffma2(a01, p, h0.x); ffma2(a23, p, h0.y);
    }

    float4 acc;
    asm("mov.b64 {%0, %1}, %2;" : "=f"(acc.x), "=f"(acc.y) : "l"(a01));
    asm("mov.b64 {%0, %1}, %2;" : "=f"(acc.z), "=f"(acc.w) : "l"(a23));
    float4 b = *reinterpret_cast<const float4*>(bias + lane * 4);
    acc.x += b.x; acc.y += b.y; acc.z += b.z; acc.w += b.w;
    acc.x = acc.x > 0.f ? acc.x : expm1f(acc.x);
    acc.y = acc.y > 0.f ? acc.y : expm1f(acc.y);
    acc.z = acc.z > 0.f ? acc.z : expm1f(acc.z);
    acc.w = acc.w > 0.f ? acc.w : expm1f(acc.w);
    *reinterpret_cast<float4*>(Xout + w * 128 + lane * 4) = acc;
}

// ---------------- edge kernel, 1 head x 32 ch (final layer) ----------------
// Tail: resets g_deg[w] = 0 so the next replay starts from a clean state.
__global__ __launch_bounds__(WPB * 32, 12)
void k_edge1(const float* __restrict__ H2, const float* __restrict__ bias,
             float* __restrict__ Out) {
    __shared__ __align__(16) float cache[WPB][CACHE_MAX];
    __shared__ __align__(16) int   ssm[WPB][CACHE_MAX];
    int wl = threadIdx.x >> 5;
    int lane = threadIdx.x & 31;
    int w = (blockIdx.x * blockDim.x + threadIdx.x) >> 5;
    if (w >= Nn) return;
    int deg = min(g_deg[w], ELLW);
    const int* srow = g_esrc + (size_t)w * ELLW;
    float adv = g_ad2[w];
    float acc = 0.f;

    float psum = 0.f;
    for (int eo = lane; eo < deg; eo += 32) {
        int src = srow[eo];
        ssm[wl][eo] = src << 5;                    // src*32
        float ev = fexp(lrelu(__ldg(g_as2 + src) + adv));
        cache[wl][eo] = ev;
        psum += ev;
    }
    #pragma unroll
    for (int o = 16; o; o >>= 1) psum += __shfl_xor_sync(0xffffffffu, psum, o);
    float inv = 1.f / psum;
    for (int eo = lane; eo < deg; eo += 32) cache[wl][eo] *= inv;
    __syncwarp();
    int eo = 0;
    for (; eo + 4 <= deg; eo += 4) {
        int4 s4 = *reinterpret_cast<const int4*>(&ssm[wl][eo]);
        float4 a4 = *reinterpret_cast<const float4*>(&cache[wl][eo]);
        float h0 = H2[s4.x + lane];
        float h1 = H2[s4.y + lane];
        float h2 = H2[s4.z + lane];
        float h3 = H2[s4.w + lane];
        acc = fmaf(a4.x, h0, acc);
        acc = fmaf(a4.y, h1, acc);
        acc = fmaf(a4.z, h2, acc);
        acc = fmaf(a4.w, h3, acc);
    }
    for (; eo < deg; eo++)
        acc = fmaf(cache[wl][eo], H2[ssm[wl][eo] + lane], acc);
    Out[w * 32 + lane] = acc + bias[lane];
    if (lane == 0) g_deg[w] = 0;                   // reset for next replay
}

// ---------------- launch ----------------
extern "C" void kernel_launch(void* const* d_in, const int* in_sizes, int n_in,
                              void* d_out, int out_size) {
    const float* x   = (const float*)d_in[0];
    const int*   ei  = (const int*)  d_in[1];
    const float* W0  = (const float*)d_in[2];
    const float* as0 = (const float*)d_in[3];
    const float* ad0 = (const float*)d_in[4];
    const float* b0  = (const float*)d_in[5];
    const float* W1  = (const float*)d_in[6];
    const float* as1 = (const float*)d_in[7];
    const float* ad1 = (const float*)d_in[8];
    const float* b1  = (const float*)d_in[9];
    const float* W2  = (const float*)d_in[10];
    const float* as2 = (const float*)d_in[11];
    const float* ad2 = (const float*)d_in[12];
    const float* b2  = (const float*)d_in[13];

    float* out        = (float*)d_out;
    float* alpha0_out = out;                        // [EP, 4]
    float* final_out  = out + (size_t)EP * 4;       // [Nn, 32]

    float *p_h, *p_x1, *p_h2;
    cudaGetSymbolAddress((void**)&p_h,  g_h);
    cudaGetSymbolAddress((void**)&p_x1, g_x1);
    cudaGetSymbolAddress((void**)&p_h2, g_h2);

    const int GEMM128_SMEM = 128 * 128 * 4 + 64 * 132 * 4;   // 99328 B
    cudaFuncSetAttribute(k_gemm128, cudaFuncAttributeMaxDynamicSharedMemorySize,
                         GEMM128_SMEM);

    const int EB = WPB * 32;                 // 128 threads per edge block
    const int EGRID = (Nn + WPB - 1) / WPB;  // one warp per node

    // (1) ELL build — g_deg zeroed by previous run's k_edge1 (or static init)
    k_fill<<<(EP + 255) / 256, 256>>>(ei);

    // (2) layer 0 GEMM
    k_gemm128<<<(Nn + 63) / 64, 256, GEMM128_SMEM>>>(x, W0, p_h, as0, ad0);

    // (3) layer 0 edge
    k_edge4<true><<<EGRID, EB>>>(p_h, b0, p_x1, alpha0_out);

    // (4) layer 1 GEMM  <- profiler's sampled slot: verify the conflict fix here
    k_gemm128<<<(Nn + 63) / 64, 256, GEMM128_SMEM>>>(p_x1, W1, p_h, as1, ad1);

    // (5) layer 1 edge
    k_edge4<false><<<EGRID, EB>>>(p_h, b1, p_x1, nullptr);

    // (6,7) layer 2
    k_gemm32<<<(Nn + 63) / 64, 512>>>(p_x1, W2, p_h2, as2, ad2);
    k_edge1<<<EGRID, EB>>>(p_h2, b2, final_out);
}

// round 14
// speedup vs baseline: 1.2762x; 1.1089x over previous
#include <cuda_runtime.h>
#include <math.h>
#include <stdint.h>

#define Nn 50000
#define Ee 1600000
#define EP 1650000          // Ee + Nn self loops
#define ELLW 128            // padded row width (deg ~ Poisson(33); max ~60 on this input)
#define CACHE_MAX 128
#define WPB 4               // warps per block in edge kernels

// ---------------- device scratch (static, no allocation) ----------------
__device__ int   g_deg[Nn];                  // zero-init; reset by k_edge1 tail each run
__device__ int   g_esrc[(size_t)Nn * ELLW];  // src per dst row (SoA)
__device__ int   g_eeid[(size_t)Nn * ELLW];  // edge id per dst row (SoA)
__device__ float g_h [Nn * 128];
__device__ float g_x1[Nn * 128];
__device__ float g_h2[Nn * 32];
__device__ float g_asrc[Nn * 4];
__device__ float g_adst[Nn * 4];
__device__ float g_as2[Nn];
__device__ float g_ad2[Nn];

// ---------------- helpers ----------------
__device__ __forceinline__ float lrelu(float x) { return x > 0.f ? x : 0.2f * x; }

// FMA-only exp (no MUFU). Valid for x <= ~30; clamps below -80 (result ~0).
__device__ __forceinline__ float fexp(float x) {
    x = fmaxf(x, -80.0f);
    float t = x * 1.4426950408889634f;
    float r = t + 12582912.0f;                 // round-to-nearest via magic number
    int   n = __float_as_int(r) - 0x4B400000;
    float f = t - (r - 12582912.0f);           // f in [-0.5, 0.5]
    float p = 0.0013333558f;
    p = fmaf(p, f, 0.0096181291f);
    p = fmaf(p, f, 0.0555041087f);
    p = fmaf(p, f, 0.2402265070f);
    p = fmaf(p, f, 0.6931471806f);
    p = fmaf(p, f, 1.0f);
    return __int_as_float((n + 127) << 23) * p;
}

__device__ __forceinline__ void ffma2(unsigned long long& d, unsigned long long a,
                                      unsigned long long b) {
    asm("fma.rn.f32x2 %0, %1, %2, %0;" : "+l"(d) : "l"(a), "l"(b));
}
__device__ __forceinline__ unsigned long long pack2(float v) {
    unsigned long long p;
    asm("mov.b64 %0, {%1, %1};" : "=l"(p) : "r"(__float_as_uint(v)));
    return p;
}

// ---------------- ELL build (single kernel; g_deg pre-zeroed) ----------------
__global__ void k_fill(const int* __restrict__ ei) {
    int e = blockIdx.x * blockDim.x + threadIdx.x;
    if (e >= EP) return;
    int src, dst;
    if (e < Ee) { src = ei[e]; dst = ei[Ee + e]; }
    else        { src = dst = e - Ee; }
    int slot = atomicAdd(&g_deg[dst], 1);
    if (slot < ELLW) {
        size_t p = (size_t)dst * ELLW + slot;
        g_esrc[p] = src;
        g_eeid[p] = e;
    }
}

// ---------------- GEMM 128x128, W staged in SMEM, fused alpha epilogue ----------
// 128-row tile, 8 rows x 8 cols per thread. Cols split into two 4-col groups
// (ct*4, 64+ct*4): W LDS 16B-spaced -> conflict-free. X reads are rt-broadcast.
// W traffic amortized over 2x rows vs round-13 (smem wf/FMA ratio 160->96).
__global__ __launch_bounds__(256)
void k_gemm128(const float* __restrict__ X, const float* __restrict__ W,
               float* __restrict__ Y,
               const float* __restrict__ as, const float* __restrict__ ad) {
    extern __shared__ float dyn[];
    float* ws = dyn;                               // [128][128] W
    float* xs = dyn + 128 * 128;                   // [128][128] X tile
    int ct = threadIdx.x & 15, rt = threadIdx.x >> 4;
    int lane = threadIdx.x & 31;
    int row0 = blockIdx.x * 128;
    // stage W (64KB)
    for (int i = 0; i < 16; i++) {
        int idx = threadIdx.x + i * 256;
        reinterpret_cast<float4*>(ws)[idx] = reinterpret_cast<const float4*>(W)[idx];
    }
    // stage X tile (64KB), zero-padded past Nn
    for (int i = 0; i < 16; i++) {
        int idx = threadIdx.x + i * 256;           // float4 index
        int r = idx >> 5;
        int gr = row0 + r;
        reinterpret_cast<float4*>(xs)[idx] =
            (gr < Nn) ? reinterpret_cast<const float4*>(X)[(size_t)gr * 32 + (idx & 31)]
                      : make_float4(0.f, 0.f, 0.f, 0.f);
    }
    __syncthreads();
    int r0 = rt * 8;
    int cA = ct * 4;            // group A cols (heads 0-1)
    int cB = 64 + ct * 4;       // group B cols (heads 2-3)
    unsigned long long acc[8][4];
    #pragma unroll
    for (int r = 0; r < 8; r++)
        #pragma unroll
        for (int c = 0; c < 4; c++) acc[r][c] = 0ull;

    const float* wsA = ws + cA;
    const float* wsB = ws + cB;
    for (int k4 = 0; k4 < 32; k4++) {
        int k = k4 * 4;
        float4 xv[8];
        #pragma unroll
        for (int r = 0; r < 8; r++)
            xv[r] = *reinterpret_cast<const float4*>(xs + (r0 + r) * 128 + k);
        #pragma unroll
        for (int kk = 0; kk < 4; kk++) {
            ulonglong2 wa = *reinterpret_cast<const ulonglong2*>(wsA + (k + kk) * 128);
            ulonglong2 wb = *reinterpret_cast<const ulonglong2*>(wsB + (k + kk) * 128);
            #pragma unroll
            for (int r = 0; r < 8; r++) {
                float xsc = kk == 0 ? xv[r].x : kk == 1 ? xv[r].y
                          : kk == 2 ? xv[r].z : xv[r].w;
                unsigned long long xp = pack2(xsc);
                ffma2(acc[r][0], xp, wa.x);
                ffma2(acc[r][1], xp, wa.y);
                ffma2(acc[r][2], xp, wb.x);
                ffma2(acc[r][3], xp, wb.y);
            }
        }
    }
    float asvA[4], advA[4], asvB[4], advB[4];
    #pragma unroll
    for (int c = 0; c < 4; c++) {
        asvA[c] = as[cA + c]; advA[c] = ad[cA + c];
        asvB[c] = as[cB + c]; advB[c] = ad[cB + c];
    }
    int headA = ct >> 3;        // 0 or 1; headB = 2 + headA

    #pragma unroll
    for (int r = 0; r < 8; r++) {
        int gr = row0 + r0 + r;
        float o[8];
        #pragma unroll
        for (int c = 0; c < 4; c++)
            asm("mov.b64 {%0, %1}, %2;" : "=f"(o[2 * c]), "=f"(o[2 * c + 1]) : "l"(acc[r][c]));
        if (gr < Nn) {
            *reinterpret_cast<float4*>(Y + (size_t)gr * 128 + cA) =
                make_float4(o[0], o[1], o[2], o[3]);
            *reinterpret_cast<float4*>(Y + (size_t)gr * 128 + cB) =
                make_float4(o[4], o[5], o[6], o[7]);
        }
        // fused alpha: head dot = 8 lanes (same rt, ct group of 8) x 4 cols
        float psAA = 0.f, psDA = 0.f, psAB = 0.f, psDB = 0.f;
        #pragma unroll
        for (int c = 0; c < 4; c++) {
            psAA = fmaf(o[c], asvA[c], psAA);
            psDA = fmaf(o[c], advA[c], psDA);
            psAB = fmaf(o[4 + c], asvB[c], psAB);
            psDB = fmaf(o[4 + c], advB[c], psDB);
        }
        #pragma unroll
        for (int off = 1; off < 8; off <<= 1) {
            psAA += __shfl_xor_sync(0xffffffffu, psAA, off);
            psDA += __shfl_xor_sync(0xffffffffu, psDA, off);
            psAB += __shfl_xor_sync(0xffffffffu, psAB, off);
            psDB += __shfl_xor_sync(0xffffffffu, psDB, off);
        }
        if ((lane & 7) == 0 && gr < Nn) {
            g_asrc[gr * 4 + headA]     = psAA;
            g_adst[gr * 4 + headA]     = psDA;
            g_asrc[gr * 4 + 2 + headA] = psAB;
            g_adst[gr * 4 + 2 + headA] = psDB;
        }
    }
}

// ---------------- GEMM: Y[N,32] = X[N,128] @ W[128,32], fused alpha1 ----------
__global__ void k_gemm32(const float* __restrict__ X, const float* __restrict__ W,
                         float* __restrict__ Y,
                         const float* __restrict__ as, const float* __restrict__ ad) {
    constexpr int CG = 8;
    constexpr int RT = 64;
    __shared__ float xs[RT][129];
    __shared__ float wsm[128 * 32];
    int tx = threadIdx.x % CG;
    int ty = threadIdx.x / CG;
    int lane = threadIdx.x & 31;
    int row0 = blockIdx.x * RT;
    for (int idx = threadIdx.x; idx < 128 * 8; idx += 512)
        reinterpret_cast<float4*>(wsm)[idx] = reinterpret_cast<const float4*>(W)[idx];
    for (int idx = threadIdx.x; idx < RT * 128; idx += 512) {
        int r = idx >> 7, c = idx & 127;
        int gr = row0 + r;
        xs[r][c] = (gr < Nn) ? X[gr * 128 + c] : 0.f;
    }
    __syncthreads();
    float4 acc = make_float4(0.f, 0.f, 0.f, 0.f);
    #pragma unroll 16
    for (int k = 0; k < 128; k++) {
        float xv = xs[ty][k];
        float4 w4 = *reinterpret_cast<const float4*>(wsm + k * 32 + tx * 4);
        acc.x = fmaf(xv, w4.x, acc.x);
        acc.y = fmaf(xv, w4.y, acc.y);
        acc.z = fmaf(xv, w4.z, acc.z);
        acc.w = fmaf(xv, w4.w, acc.w);
    }
    int gr = row0 + ty;
    if (gr < Nn)
        *reinterpret_cast<float4*>(Y + gr * 32 + tx * 4) = acc;
    float4 a4 = *reinterpret_cast<const float4*>(as + tx * 4);
    float4 d4 = *reinterpret_cast<const float4*>(ad + tx * 4);
    float psA = acc.x * a4.x + acc.y * a4.y + acc.z * a4.z + acc.w * a4.w;
    float psD = acc.x * d4.x + acc.y * d4.y + acc.z * d4.z + acc.w * d4.w;
    #pragma unroll
    for (int o = 4; o; o >>= 1) {
        psA += __shfl_xor_sync(0xffffffffu, psA, o);
        psD += __shfl_xor_sync(0xffffffffu, psD, o);
    }
    if ((lane & 7) == 0 && gr < Nn) { g_as2[gr] = psA; g_ad2[gr] = psD; }
}

// ---------------- edge kernel, 4 heads x 32 ch (one warp per dst) ----------------
template<bool WRITE_ALPHA>
__global__ __launch_bounds__(WPB * 32, 12)
void k_edge4(const float* __restrict__ H, const float* __restrict__ bias,
             float* __restrict__ Xout, float* __restrict__ alpha_out) {
    __shared__ __align__(16) float cacheT[WPB][4][CACHE_MAX];  // [head][edge] alphas
    __shared__ __align__(16) int   ssm[WPB][CACHE_MAX];        // src*32
    int wl = threadIdx.x >> 5;
    int lane = threadIdx.x & 31;
    int w = (blockIdx.x * blockDim.x + threadIdx.x) >> 5;
    if (w >= Nn) return;
    int deg = min(g_deg[w], ELLW);
    const int* srow = g_esrc + (size_t)w * ELLW;
    float4 advv = *reinterpret_cast<const float4*>(g_adst + 4 * w);
    int head = lane >> 3;
    float adh = head == 0 ? advv.x : head == 1 ? advv.y : head == 2 ? advv.z : advv.w;
    const float4* H4 = reinterpret_cast<const float4*>(H);

    for (int eo = lane; eo < deg; eo += 32)
        ssm[wl][eo] = srow[eo] << 5;               // src*32: gather idx = ssm + lane
    __syncwarp();

    float psum = 0.f;
    for (int eo = lane & 7; eo < deg; eo += 8) {
        int src4 = ssm[wl][eo] >> 3;               // src*4
        float ev = fexp(lrelu(__ldg(g_asrc + src4 + head) + adh));
        cacheT[wl][head][eo] = ev;
        psum += ev;
    }
    psum += __shfl_xor_sync(0xffffffffu, psum, 1);
    psum += __shfl_xor_sync(0xffffffffu, psum, 2);
    psum += __shfl_xor_sync(0xffffffffu, psum, 4);
    float inv = 1.f / psum;
    for (int eo = lane & 7; eo < deg; eo += 8)
        cacheT[wl][head][eo] *= inv;               // cache now holds alpha
    __syncwarp();

    if (WRITE_ALPHA) {
        const int* erow = g_eeid + (size_t)w * ELLW;
        for (int eo = lane; eo < deg; eo += 32) {
            int eid = erow[eo];
            float4 av = make_float4(cacheT[wl][0][eo], cacheT[wl][1][eo],
                                    cacheT[wl][2][eo], cacheT[wl][3][eo]);
            *reinterpret_cast<float4*>(alpha_out + (size_t)eid * 4) = av;
        }
    }

    unsigned long long a01 = 0ull, a23 = 0ull;
    const float* ct = cacheT[wl][head];
    int eo = 0;
    for (; eo + 8 <= deg; eo += 8) {
        int4 sa = *reinterpret_cast<const int4*>(&ssm[wl][eo]);
        int4 sb = *reinterpret_cast<const int4*>(&ssm[wl][eo + 4]);
        float4 aa = *reinterpret_cast<const float4*>(ct + eo);
        float4 ab = *reinterpret_cast<const float4*>(ct + eo + 4);
        ulonglong2 h0 = *reinterpret_cast<const ulonglong2*>(H4 + sa.x + lane);
        ulonglong2 h1 = *reinterpret_cast<const ulonglong2*>(H4 + sa.y + lane);
        ulonglong2 h2 = *reinterpret_cast<const ulonglong2*>(H4 + sa.z + lane);
        ulonglong2 h3 = *reinterpret_cast<const ulonglong2*>(H4 + sa.w + lane);
        ulonglong2 h4 = *reinterpret_cast<const ulonglong2*>(H4 + sb.x + lane);
        ulonglong2 h5 = *reinterpret_cast<const ulonglong2*>(H4 + sb.y + lane);
        ulonglong2 h6 = *reinterpret_cast<const ulonglong2*>(H4 + sb.z + lane);
        ulonglong2 h7 = *reinterpret_cast<const ulonglong2*>(H4 + sb.w + lane);
        unsigned long long p;
        p = pack2(aa.x); ffma2(a01, p, h0.x); ffma2(a23, p, h0.y);
        p = pack2(aa.y); ffma2(a01, p, h1.x); ffma2(a23, p, h1.y);
        p = pack2(aa.z); ffma2(a01, p, h2.x); ffma2(a23, p, h2.y);
        p = pack2(aa.w); ffma2(a01, p, h3.x); ffma2(a23, p, h3.y);
        p = pack2(ab.x); ffma2(a01, p, h4.x); ffma2(a23, p, h4.y);
        p = pack2(ab.y); ffma2(a01, p, h5.x); ffma2(a23, p, h5.y);
        p = pack2(ab.z); ffma2(a01, p, h6.x); ffma2(a23, p, h6.y);
        p = pack2(ab.w); ffma2(a01, p, h7.x); ffma2(a23, p, h7.y);
    }
    for (; eo + 4 <= deg; eo += 4) {
        int4 sa = *reinterpret_cast<const int4*>(&ssm[wl][eo]);
        float4 aa = *reinterpret_cast<const float4*>(ct + eo);
        ulonglong2 h0 = *reinterpret_cast<const ulonglong2*>(H4 + sa.x + lane);
        ulonglong2 h1 = *reinterpret_cast<const ulonglong2*>(H4 + sa.y + lane);
        ulonglong2 h2 = *reinterpret_cast<const ulonglong2*>(H4 + sa.z + lane);
        ulonglong2 h3 = *reinterpret_cast<const ulonglong2*>(H4 + sa.w + lane);
        unsigned long long p;
        p = pack2(aa.x); ffma2(a01, p, h0.x); ffma2(a23, p, h0.y);
        p = pack2(aa.y); ffma2(a01, p, h1.x); ffma2(a23, p, h1.y);
        p = pack2(aa.z); ffma2(a01, p, h2.x); ffma2(a23, p, h2.y);
        p = pack2(aa.w); ffma2(a01, p, h3.x); ffma2(a23, p, h3.y);
    }
    for (; eo < deg; eo++) {
        ulonglong2 h0 = *reinterpret_cast<const ulonglong2*>(H4 + ssm[wl][eo] + lane);
        unsigned long long p = pack2(ct[eo]);
        ffma2(a01, p, h0.x); ffma2(a23, p, h0.y);
    }

    float4 acc;
    asm("mov.b64 {%0, %1}, %2;" : "=f"(acc.x), "=f"(acc.y) : "l"(a01));
    asm("mov.b64 {%0, %1}, %2;" : "=f"(acc.z), "=f"(acc.w) : "l"(a23));
    float4 b = *reinterpret_cast<const float4*>(bias + lane * 4);
    acc.x += b.x; acc.y += b.y; acc.z += b.z; acc.w += b.w;
    acc.x = acc.x > 0.f ? acc.x : expm1f(acc.x);
    acc.y = acc.y > 0.f ? acc.y : expm1f(acc.y);
    acc.z = acc.z > 0.f ? acc.z : expm1f(acc.z);
    acc.w = acc.w > 0.f ? acc.w : expm1f(acc.w);
    *reinterpret_cast<float4*>(Xout + w * 128 + lane * 4) = acc;
}

// ---------------- edge kernel, 1 head x 32 ch (final layer) ----------------
// Tail: resets g_deg[w] = 0 so the next replay starts from a clean state.
__global__ __launch_bounds__(WPB * 32, 12)
void k_edge1(const float* __restrict__ H2, const float* __restrict__ bias,
             float* __restrict__ Out) {
    __shared__ __align__(16) float cache[WPB][CACHE_MAX];
    __shared__ __align__(16) int   ssm[WPB][CACHE_MAX];
    int wl = threadIdx.x >> 5;
    int lane = threadIdx.x & 31;
    int w = (blockIdx.x * blockDim.x + threadIdx.x) >> 5;
    if (w >= Nn) return;
    int deg = min(g_deg[w], ELLW);
    const int* srow = g_esrc + (size_t)w * ELLW;
    float adv = g_ad2[w];
    float acc = 0.f;

    float psum = 0.f;
    for (int eo = lane; eo < deg; eo += 32) {
        int src = srow[eo];
        ssm[wl][eo] = src << 5;                    // src*32
        float ev = fexp(lrelu(__ldg(g_as2 + src) + adv));
        cache[wl][eo] = ev;
        psum += ev;
    }
    #pragma unroll
    for (int o = 16; o; o >>= 1) psum += __shfl_xor_sync(0xffffffffu, psum, o);
    float inv = 1.f / psum;
    for (int eo = lane; eo < deg; eo += 32) cache[wl][eo] *= inv;
    __syncwarp();
    int eo = 0;
    for (; eo + 4 <= deg; eo += 4) {
        int4 s4 = *reinterpret_cast<const int4*>(&ssm[wl][eo]);
        float4 a4 = *reinterpret_cast<const float4*>(&cache[wl][eo]);
        float h0 = H2[s4.x + lane];
        float h1 = H2[s4.y + lane];
        float h2 = H2[s4.z + lane];
        float h3 = H2[s4.w + lane];
        acc = fmaf(a4.x, h0, acc);
        acc = fmaf(a4.y, h1, acc);
        acc = fmaf(a4.z, h2, acc);
        acc = fmaf(a4.w, h3, acc);
    }
    for (; eo < deg; eo++)
        acc = fmaf(cache[wl][eo], H2[ssm[wl][eo] + lane], acc);
    Out[w * 32 + lane] = acc + bias[lane];
    if (lane == 0) g_deg[w] = 0;                   // reset for next replay
}

// ---------------- launch ----------------
extern "C" void kernel_launch(void* const* d_in, const int* in_sizes, int n_in,
                              void* d_out, int out_size) {
    const float* x   = (const float*)d_in[0];
    const int*   ei  = (const int*)  d_in[1];
    const float* W0  = (const float*)d_in[2];
    const float* as0 = (const float*)d_in[3];
    const float* ad0 = (const float*)d_in[4];
    const float* b0  = (const float*)d_in[5];
    const float* W1  = (const float*)d_in[6];
    const float* as1 = (const float*)d_in[7];
    const float* ad1 = (const float*)d_in[8];
    const float* b1  = (const float*)d_in[9];
    const float* W2  = (const float*)d_in[10];
    const float* as2 = (const float*)d_in[11];
    const float* ad2 = (const float*)d_in[12];
    const float* b2  = (const float*)d_in[13];

    float* out        = (float*)d_out;
    float* alpha0_out = out;                        // [EP, 4]
    float* final_out  = out + (size_t)EP * 4;       // [Nn, 32]

    float *p_h, *p_x1, *p_h2;
    cudaGetSymbolAddress((void**)&p_h,  g_h);
    cudaGetSymbolAddress((void**)&p_x1, g_x1);
    cudaGetSymbolAddress((void**)&p_h2, g_h2);

    const int GEMM128_SMEM = 128 * 128 * 4 * 2;    // W 64KB + X tile 64KB = 131072 B
    cudaFuncSetAttribute(k_gemm128, cudaFuncAttributeMaxDynamicSharedMemorySize,
                         GEMM128_SMEM);

    const int EB = WPB * 32;                 // 128 threads per edge block
    const int EGRID = (Nn + WPB - 1) / WPB;  // one warp per node
    const int GGRID = (Nn + 127) / 128;      // 128-row GEMM tiles

    // (1) ELL build — g_deg zeroed by previous run's k_edge1 (or static init)
    k_fill<<<(EP + 255) / 256, 256>>>(ei);

    // (2) layer 0 GEMM
    k_gemm128<<<GGRID, 256, GEMM128_SMEM>>>(x, W0, p_h, as0, ad0);

    // (3) layer 0 edge
    k_edge4<true><<<EGRID, EB>>>(p_h, b0, p_x1, alpha0_out);

    // (4) layer 1 GEMM  <- profiler's sampled slot: verify the W-amortization here
    k_gemm128<<<GGRID, 256, GEMM128_SMEM>>>(p_x1, W1, p_h, as1, ad1);

    // (5) layer 1 edge
    k_edge4<false><<<EGRID, EB>>>(p_h, b1, p_x1, nullptr);

    // (6,7) layer 2
    k_gemm32<<<(Nn + 63) / 64, 512>>>(p_x1, W2, p_h2, as2, ad2);
    k_edge1<<<EGRID, EB>>>(p_h2, b2, final_out);
}